// round 3
// baseline (speedup 1.0000x reference)
#include <cuda_runtime.h>

#define THREADS 256
#define Jt 32
#define NT 32          // 1024 / Jt
#define DEPTH 3

typedef unsigned long long u64;
typedef unsigned int u32;

__device__ __forceinline__ float tanh_apx(float x) {
    float r; asm("tanh.approx.f32 %0, %1;" : "=f"(r) : "f"(x)); return r;
}
#define FMA2(d,a,b,c)  asm("fma.rn.f32x2 %0, %1, %2, %3;" : "=l"(d) : "l"(a), "l"(b), "l"(c))
#define PACK2(d,x,y)   asm("mov.b64 %0, {%1,%2};" : "=l"(d) : "f"(x), "f"(y))
#define UNPACK2(x,y,d) asm("mov.b64 {%0,%1}, %2;" : "=f"(x), "=f"(y) : "l"(d))
#define CP16(dst,src)  asm volatile("cp.async.cg.shared.global [%0], [%1], 16;" :: "r"(dst), "l"(src))
#define CPCOMMIT()     asm volatile("cp.async.commit_group;")
#define CPWAIT1()      asm volatile("cp.async.wait_group 1;")

__global__ __launch_bounds__(THREADS, 2)
void attn_mlp_kernel(const float* __restrict__ Q, const float* __restrict__ K,
                     const float* __restrict__ bias, const float* __restrict__ mask,
                     float* __restrict__ out, float* __restrict__ attn)
{
    // K tile ring: 3 x (32 j-rows x 17 float4), padded stride 17 -> low-conflict
    __shared__ float4 ksm[DEPTH][Jt * 17];
    __shared__ float  red[8 * 128];          // [warp][row][ch]
    __shared__ float  cbuf[2][8];

    const int tid = threadIdx.x;
    const int w   = tid >> 5, l = tid & 31;
    const int cg  = l >> 2;              // channel group: 8 channels
    const int jw  = l & 3;               // j within warp
    const int jl  = w * 4 + jw;          // j within tile (0..31)

    const int row0 = blockIdx.x * 2;     // two i-rows per block, same b
    const int b    = row0 >> 10;

    // prescaled q (x0.5) and bias, packed f32x2; 8 channels per thread
    u64 q0[4], q1[4], bb[4], s0[4], s1[4];
    {
        const float* q0p = Q + (size_t)row0 * 64 + cg * 8;
        const float* q1p = q0p + 64;
        const float* bp  = bias + cg * 8;
#pragma unroll
        for (int p = 0; p < 4; ++p) {
            PACK2(q0[p], 0.5f * q0p[2*p], 0.5f * q0p[2*p+1]);
            PACK2(q1[p], 0.5f * q1p[2*p], 0.5f * q1p[2*p+1]);
            PACK2(bb[p], 0.5f * bp[2*p],  0.5f * bp[2*p+1]);
            s0[p] = 0ull; s1[p] = 0ull;
        }
    }
    float cnt0 = 0.f, cnt1 = 0.f;

    const float4* Kg  = (const float4*)K + (size_t)b * 1024 * 16;
    const float*  m0p = mask + (size_t)row0 * 1024;
    const float*  m1p = m0p + 1024;
    float*        a0p = attn + (size_t)row0 * 1024;
    float*        a1p = a0p + 1024;

    const u32 ksm_base = (u32)__cvta_generic_to_shared(ksm);
    const int f0 = tid, f1 = tid + 256;                 // 2 float4 per thread per tile
    const u32 d0off = ((u32)((f0 >> 4) * 17 + (f0 & 15))) << 4;
    const u32 d1off = ((u32)((f1 >> 4) * 17 + (f1 & 15))) << 4;

    // prologue: prefetch tiles 0 and 1
#pragma unroll
    for (int t = 0; t < 2; ++t) {
        u32 base = ksm_base + t * (Jt * 17 * 16);
        CP16(base + d0off, (const void*)(Kg + (size_t)(t * Jt + (f0 >> 4)) * 16 + (f0 & 15)));
        CP16(base + d1off, (const void*)(Kg + (size_t)(t * Jt + (f1 >> 4)) * 16 + (f1 & 15)));
        CPCOMMIT();
    }

    int buf = 0;
    for (int tile = 0; tile < NT; ++tile) {
        CPWAIT1();               // tile's group done (<=1 newer pending)
        __syncthreads();

        // prefetch tile+2 into ring slot (always commit: keeps group count in sync)
        if (tile + 2 < NT) {
            int nb = buf + 2; if (nb >= DEPTH) nb -= DEPTH;
            u32 base = ksm_base + nb * (Jt * 17 * 16);
            CP16(base + d0off, (const void*)(Kg + (size_t)((tile + 2) * Jt + (f0 >> 4)) * 16 + (f0 & 15)));
            CP16(base + d1off, (const void*)(Kg + (size_t)((tile + 2) * Jt + (f1 >> 4)) * 16 + (f1 & 15)));
        }
        CPCOMMIT();

        const int   j  = tile * Jt + jl;
        const float m0 = m0p[j], m1 = m1p[j];

        const u64* kb = (const u64*)(ksm[buf]) + jl * 34 + cg * 4;  // row stride 68 floats
        u64 k2[4];
#pragma unroll
        for (int p = 0; p < 4; ++p) k2[p] = kb[p];

        u64 m20, m21; PACK2(m20, m0, m0); PACK2(m21, m1, m1);
        u64 dp0 = 0ull, dp1 = 0ull;

#pragma unroll
        for (int p = 0; p < 4; ++p) {
            u64 l2, t2; float la, lb, ta, tb;
            FMA2(l2, q0[p], k2[p], bb[p]);
            FMA2(dp0, q0[p], k2[p], dp0);
            UNPACK2(la, lb, l2);
            ta = tanh_apx(la); tb = tanh_apx(lb);
            PACK2(t2, ta, tb);
            FMA2(s0[p], m20, t2, s0[p]);

            FMA2(l2, q1[p], k2[p], bb[p]);
            FMA2(dp1, q1[p], k2[p], dp1);
            UNPACK2(la, lb, l2);
            ta = tanh_apx(la); tb = tanh_apx(lb);
            PACK2(t2, ta, tb);
            FMA2(s1[p], m21, t2, s1[p]);
        }
        if (l < 4) { cnt0 += m0; cnt1 += m1; }

        // attention logits: q was prescaled by 0.5 -> attn = 2*dot*mask (exact fp32 path)
        float dx, dy;
        UNPACK2(dx, dy, dp0); float d0 = dx + dy;
        UNPACK2(dx, dy, dp1); float d1 = dx + dy;
        d0 += __shfl_xor_sync(~0u, d0, 4);
        d0 += __shfl_xor_sync(~0u, d0, 8);
        d0 += __shfl_xor_sync(~0u, d0, 16);
        d1 += __shfl_xor_sync(~0u, d1, 4);
        d1 += __shfl_xor_sync(~0u, d1, 8);
        d1 += __shfl_xor_sync(~0u, d1, 16);
        if (l < 4) {
            a0p[j] = (d0 + d0) * m0;
            a1p[j] = (d1 + d1) * m1;
        }
        if (++buf == DEPTH) buf = 0;
    }

    // ---- final reductions ----
    // sum accumulators over the 4 j-lanes (xor 1,2), writer = jw==0 lane of each cg
#pragma unroll
    for (int p = 0; p < 4; ++p) {
        float x0, y0, x1, y1;
        UNPACK2(x0, y0, s0[p]); UNPACK2(x1, y1, s1[p]);
#pragma unroll
        for (int o = 1; o <= 2; o <<= 1) {
            x0 += __shfl_xor_sync(~0u, x0, o);
            y0 += __shfl_xor_sync(~0u, y0, o);
            x1 += __shfl_xor_sync(~0u, x1, o);
            y1 += __shfl_xor_sync(~0u, y1, o);
        }
        if (jw == 0) {
            float* rp = red + w * 128 + cg * 8 + 2 * p;
            rp[0]      = x0;
            rp[1]      = y0;
            rp[64]     = x1;
            rp[64 + 1] = y1;
        }
    }
    // mask counts live in lanes 0..3
    cnt0 += __shfl_xor_sync(~0u, cnt0, 1);
    cnt0 += __shfl_xor_sync(~0u, cnt0, 2);
    cnt1 += __shfl_xor_sync(~0u, cnt1, 1);
    cnt1 += __shfl_xor_sync(~0u, cnt1, 2);
    if (l == 0) { cbuf[0][w] = cnt0; cbuf[1][w] = cnt1; }
    __syncthreads();

    if (tid < 128) {
        const int r  = tid >> 6;
        const int ch = tid & 63;
        float ct = 0.f, s = 0.f;
#pragma unroll
        for (int ww = 0; ww < 8; ++ww) {
            ct += cbuf[r][ww];
            s  += red[ww * 128 + r * 64 + ch];
        }
        // output = 0.5 + 0.5 * sum(m*tanh)/cnt
        out[(size_t)(row0 + r) * 64 + ch] = 0.5f + 0.5f * s / ct;
    }
}

extern "C" void kernel_launch(void* const* d_in, const int* in_sizes, int n_in,
                              void* d_out, int out_size)
{
    const float* Q    = (const float*)d_in[0];
    const float* K    = (const float*)d_in[1];
    const float* bias = (const float*)d_in[2];
    const float* mask = (const float*)d_in[3];
    float* out  = (float*)d_out;                       // [B, I, C]
    float* attn = out + (size_t)2 * 1024 * 64;         // [B, I, J]
    attn_mlp_kernel<<<1024, THREADS>>>(Q, K, bias, mask, out, attn);
}